// round 2
// baseline (speedup 1.0000x reference)
#include <cuda_runtime.h>
#include <cuda_bf16.h>

#define NTAG 9
#define SEQ  512
#define BATCH 4096

// Accumulators (device globals: no allocation allowed)
__device__ double             g_acc;    // sum over batches of (total - real)
__device__ unsigned long long g_chars;  // sum of lengths (num_chars)

__global__ void crf_init_kernel() {
    g_acc = 0.0;
    g_chars = 0ull;
}

__global__ void __launch_bounds__(32, 1) crf_main_kernel(
    const float* __restrict__ bert,  // [B, S, NTAG] f32
    const int* __restrict__ mask,    // [B, S] i32
    const int* __restrict__ tags,    // [B, S] i32 (JAX x64 disabled: int64 -> int32)
    const float* __restrict__ trans) // [11, 11] f32
{
    __shared__ float sT[121];
    const int lane = threadIdx.x;
    // Stage raw transitions in shared for dynamic (gold-path) lookups.
    for (int i = lane; i < 121; i += 32) sT[i] = trans[i];
    __syncwarp();

    const int b = blockIdx.x * 32 + lane;   // grid is exactly BATCH/32 blocks

    // E = exp(trans[:9,:9]) fully register-resident (compile-time indexed).
    float E[NTAG][NTAG];
#pragma unroll
    for (int i = 0; i < NTAG; i++)
#pragma unroll
        for (int j = 0; j < NTAG; j++)
            E[i][j] = __expf(trans[i * 11 + j]);

    const float* em = bert + (size_t)b * (SEQ * NTAG);
    const int*   mk = mask + (size_t)b * SEQ;
    const int*   tg = tags + (size_t)b * SEQ;

    // ---- length L = sum(mask) (mask is a contiguous prefix of ones) ----
    int L = 0;
    {
        const int4* mk4 = reinterpret_cast<const int4*>(mk);
#pragma unroll 4
        for (int i = 0; i < SEQ / 4; i++) {
            int4 v = mk4[i];
            L += v.x + v.y + v.z + v.w;
        }
    }

    // ---- t = 0 ----
    float alpha[NTAG];
    float e0[NTAG];
#pragma unroll
    for (int j = 0; j < NTAG; j++) e0[j] = em[j];
    int prev = tg[0];
    float real = sT[9 * 11 + prev];           // first_trans = T[start, tags[0]]
#pragma unroll
    for (int j = 0; j < NTAG; j++)            // emit at t=0 (mask[0]==1 always)
        real += (j == prev) ? e0[j] : 0.0f;
#pragma unroll
    for (int j = 0; j < NTAG; j++)
        alpha[j] = sT[9 * 11 + j] + e0[j];    // alpha0 = T[start,:] + em0

    // ---- forward scan t = 1 .. L-1 ----
    for (int t = 1; t < L; ++t) {
        const float* p_em = em + t * NTAG;
        float et[NTAG];
#pragma unroll
        for (int j = 0; j < NTAG; j++) et[j] = p_em[j];

        const int tag = tg[t];
        real += sT[prev * 11 + tag];          // mid transition
#pragma unroll
        for (int j = 0; j < NTAG; j++)        // emit gather without dyn-index
            real += (j == tag) ? et[j] : 0.0f;
        prev = tag;

        // new_j = et_j + mx + log( sum_i exp(alpha_i - mx) * E[i][j] )
        float mx = alpha[0];
#pragma unroll
        for (int i = 1; i < NTAG; i++) mx = fmaxf(mx, alpha[i]);
        float p[NTAG];
#pragma unroll
        for (int i = 0; i < NTAG; i++) p[i] = __expf(alpha[i] - mx);
#pragma unroll
        for (int j = 0; j < NTAG; j++) {
            float s = 0.0f;
#pragma unroll
            for (int i = 0; i < NTAG; i++) s = fmaf(p[i], E[i][j], s);
            alpha[j] = mx + __logf(s) + et[j];
        }
    }

    // ---- termination ----
    real += sT[prev * 11 + 10];               // T[last_tag, end]

    float v[NTAG];
#pragma unroll
    for (int j = 0; j < NTAG; j++) v[j] = alpha[j] + sT[j * 11 + 10];
    float mx = v[0];
#pragma unroll
    for (int j = 1; j < NTAG; j++) mx = fmaxf(mx, v[j]);
    float s = 0.0f;
#pragma unroll
    for (int j = 0; j < NTAG; j++) s += __expf(v[j] - mx);
    const float total = mx + __logf(s);

    // ---- reduce across the warp, one atomic per warp ----
    double contrib = (double)(total - real);
    int chars = L;
#pragma unroll
    for (int off = 16; off > 0; off >>= 1) {
        contrib += __shfl_down_sync(0xffffffffu, contrib, off);
        chars   += __shfl_down_sync(0xffffffffu, chars, off);
    }
    if (lane == 0) {
        atomicAdd(&g_acc, contrib);
        atomicAdd(&g_chars, (unsigned long long)chars);
    }
}

__global__ void crf_fin_kernel(float* out) {
    out[0] = (float)(g_acc / (double)g_chars);
}

extern "C" void kernel_launch(void* const* d_in, const int* in_sizes, int n_in,
                              void* d_out, int out_size)
{
    const float* bert  = (const float*)d_in[0];  // [4096,512,9] f32
    const int*   mask  = (const int*)d_in[1];    // [4096,512] i32
    const int*   tags  = (const int*)d_in[2];    // [4096,512] i32
    const float* trans = (const float*)d_in[3];  // [11,11] f32
    float* out = (float*)d_out;

    crf_init_kernel<<<1, 1>>>();
    crf_main_kernel<<<BATCH / 32, 32>>>(bert, mask, tags, trans);
    crf_fin_kernel<<<1, 1>>>(out);
}

// round 3
// speedup vs baseline: 1.4272x; 1.4272x over previous
#include <cuda_runtime.h>

#define NTAG 9
#define SEQ  512
#define BATCH 4096
#define NWARPS (BATCH / 32)

// Per-warp partial results (written every launch -> no init kernel needed)
__device__ double g_pacc[NWARPS];
__device__ int    g_pchars[NWARPS];

// ---------- f32x2 helpers (PTX-only packed FP32 pipe on sm_103a) ----------
__device__ __forceinline__ unsigned long long splat2(float x) {
    unsigned long long r;
    asm("mov.b64 %0, {%1, %1};" : "=l"(r) : "f"(x));
    return r;
}
__device__ __forceinline__ unsigned long long pack2(float lo, float hi) {
    unsigned long long r;
    asm("mov.b64 %0, {%1, %2};" : "=l"(r) : "f"(lo), "f"(hi));
    return r;
}
__device__ __forceinline__ void unpack2(unsigned long long v, float& lo, float& hi) {
    asm("mov.b64 {%0, %1}, %2;" : "=f"(lo), "=f"(hi) : "l"(v));
}
__device__ __forceinline__ unsigned long long mul2(unsigned long long a, unsigned long long b) {
    unsigned long long d;
    asm("mul.rn.f32x2 %0, %1, %2;" : "=l"(d) : "l"(a), "l"(b));
    return d;
}
__device__ __forceinline__ unsigned long long fma2(unsigned long long a, unsigned long long b,
                                                   unsigned long long c) {
    unsigned long long d;
    asm("fma.rn.f32x2 %0, %1, %2, %3;" : "=l"(d) : "l"(a), "l"(b), "l"(c));
    return d;
}

__global__ void __launch_bounds__(32, 1) crf_main_kernel(
    const float* __restrict__ bert,  // [B, S, 9] f32
    const int* __restrict__ mask,    // [B, S] i32
    const int* __restrict__ tags,    // [B, S] i32
    const float* __restrict__ trans) // [11, 11] f32
{
    __shared__ float sT[121];
    const int lane = threadIdx.x;
    for (int i = lane; i < 121; i += 32) sT[i] = trans[i];
    __syncwarp();

    const int b = blockIdx.x * 32 + lane;

    // E2[i][jp] = { exp(T[i][2jp]), exp(T[i][2jp+1]) }  (pad hi of jp=4 with 0)
    unsigned long long E2[NTAG][5];
#pragma unroll
    for (int i = 0; i < NTAG; i++) {
#pragma unroll
        for (int jp = 0; jp < 5; jp++) {
            float lo = __expf(trans[i * 11 + 2 * jp]);
            float hi = (2 * jp + 1 < NTAG) ? __expf(trans[i * 11 + 2 * jp + 1]) : 0.0f;
            E2[i][jp] = pack2(lo, hi);
        }
    }

    const float* em = bert + (size_t)b * (SEQ * NTAG);
    const int*   mk = mask + (size_t)b * SEQ;
    const int*   tg = tags + (size_t)b * SEQ;

    // ---- length L = sum(mask) ----
    int L = 0;
    {
        const int4* mk4 = reinterpret_cast<const int4*>(mk);
#pragma unroll 4
        for (int i = 0; i < SEQ / 4; i++) {
            int4 v = mk4[i];
            L += v.x + v.y + v.z + v.w;
        }
    }
    int maxL = L;
#pragma unroll
    for (int off = 16; off > 0; off >>= 1)
        maxL = max(maxL, __shfl_xor_sync(0xffffffffu, maxL, off));

    // ---- state ----
    float W[NTAG];     // prob-domain alpha: alpha_j = eAcc*ln2 + log(W_j)
    int   eAcc = 0;    // exact power-of-2 rescale accumulator
    float real;
    int   prev;

    // One quad = rows t0..t0+3, 36 floats, 16B-aligned when t0 % 4 == 0.
    float buf[36];
    auto load_quad = [&](int t0) {
        const float4* p = reinterpret_cast<const float4*>(em + t0 * NTAG);
#pragma unroll
        for (int k = 0; k < 9; k++) {
            float4 v = p[k];
            buf[4 * k + 0] = v.x; buf[4 * k + 1] = v.y;
            buf[4 * k + 2] = v.z; buf[4 * k + 3] = v.w;
        }
    };

    auto step = [&](int t, const float* et, int tag) {
        if (t < L) {
            // gold path: mid transition + gathered emit (L1-hit, off alpha chain)
            real += sT[prev * 11 + tag];
            real += __ldg(em + t * NTAG + tag);
            prev = tag;
            // X_j = exp(em_j)
            float X[NTAG];
#pragma unroll
            for (int j = 0; j < NTAG; j++) X[j] = __expf(et[j]);
            // matvec in probability domain: acc_j = sum_i W_i * E_ij
            unsigned long long ws[NTAG];
#pragma unroll
            for (int i = 0; i < NTAG; i++) ws[i] = splat2(W[i]);
            unsigned long long acc[5];
#pragma unroll
            for (int jp = 0; jp < 5; jp++) acc[jp] = mul2(ws[0], E2[0][jp]);
#pragma unroll
            for (int i = 1; i < NTAG; i++)
#pragma unroll
                for (int jp = 0; jp < 5; jp++) acc[jp] = fma2(ws[i], E2[i][jp], acc[jp]);
            // W'_j = acc_j * X_j
#pragma unroll
            for (int jp = 0; jp < 4; jp++) {
                float a, c;
                unpack2(acc[jp], a, c);
                W[2 * jp]     = a * X[2 * jp];
                W[2 * jp + 1] = c * X[2 * jp + 1];
            }
            {
                float a, c;
                unpack2(acc[4], a, c);
                W[8] = a * X[8];
            }
        }
    };

    // Exact rescale: divide W by 2^e (e = exponent of max W), track e in integer.
    auto rescale = [&]() {
        float mx = W[0];
#pragma unroll
        for (int j = 1; j < NTAG; j++) mx = fmaxf(mx, W[j]);
        int e = ((__float_as_int(mx) >> 23) & 255) - 127;
        eAcc += e;
        float sc = __int_as_float((127 - e) << 23);
#pragma unroll
        for (int j = 0; j < NTAG; j++) W[j] *= sc;
    };

    // ---- prologue: quad 0 (t = 0..3) ----
    load_quad(0);
    int4 tq = *reinterpret_cast<const int4*>(tg);
    prev = tq.x;
    real = sT[9 * 11 + prev] + __ldg(em + prev);     // first_trans + emit(t=0)
#pragma unroll
    for (int j = 0; j < NTAG; j++)
        W[j] = __expf(sT[9 * 11 + j] + buf[4 * j]);  // alpha0 in prob domain
    step(1, buf + 0 + 1 * 0 + 0, tq.y);              // placeholder fixed below
    // NOTE: buf layout is [k][4] transposed vs rows; fix by strided access:
    // (handled by row extractor below instead)
    ;
    // ---- re-do prologue steps with correct row extraction ----
    // buf holds quad as 9 float4s: element (row r, tag j) = buf[4*j + r]
    {
        float row[NTAG];
#pragma unroll
        for (int j = 0; j < NTAG; j++) row[j] = buf[4 * j + 1];
        // undo placeholder: step(1,...) above used wrong data only if t<L; guard:
        // (placeholder was a bug risk; we instead structure cleanly: see below)
        (void)row;
    }

    // The placeholder call above is WRONG; real implementation below uses rows.
    // -- restart state to keep correctness --
    prev = tq.x;
    real = sT[9 * 11 + prev] + __ldg(em + prev);
#pragma unroll
    for (int j = 0; j < NTAG; j++)
        W[j] = __expf(sT[9 * 11 + j] + buf[4 * j]);
    eAcc = 0;

    {
        float r1[NTAG], r2[NTAG], r3[NTAG];
#pragma unroll
        for (int j = 0; j < NTAG; j++) { r1[j] = buf[4 * j + 1]; r2[j] = buf[4 * j + 2]; r3[j] = buf[4 * j + 3]; }
        step(1, r1, tq.y);
        step(2, r2, tq.z);
        step(3, r3, tq.w);
    }
    rescale();

    // ---- main quads ----
    for (int t0 = 4; t0 < maxL; t0 += 4) {
        if (t0 < L) load_quad(t0);
        int4 tq2 = (t0 < L) ? *reinterpret_cast<const int4*>(tg + t0) : make_int4(0, 0, 0, 0);
        float r0[NTAG], r1[NTAG], r2[NTAG], r3[NTAG];
#pragma unroll
        for (int j = 0; j < NTAG; j++) {
            r0[j] = buf[4 * j + 0]; r1[j] = buf[4 * j + 1];
            r2[j] = buf[4 * j + 2]; r3[j] = buf[4 * j + 3];
        }
        step(t0 + 0, r0, tq2.x);
        step(t0 + 1, r1, tq2.y);
        step(t0 + 2, r2, tq2.z);
        step(t0 + 3, r3, tq2.w);
        rescale();
    }

    // ---- termination ----
    real += sT[prev * 11 + 10];                      // T[last_tag, end]
    float s = 0.0f;
#pragma unroll
    for (int j = 0; j < NTAG; j++) s = fmaf(W[j], __expf(sT[j * 11 + 10]), s);
    double total = (double)eAcc * 0.693147180559945309 + (double)__logf(s);
    double contrib = total - (double)real;

    int chars = L;
#pragma unroll
    for (int off = 16; off > 0; off >>= 1) {
        contrib += __shfl_down_sync(0xffffffffu, contrib, off);
        chars   += __shfl_down_sync(0xffffffffu, chars, off);
    }
    if (lane == 0) {
        g_pacc[blockIdx.x]   = contrib;
        g_pchars[blockIdx.x] = chars;
    }
}

__global__ void crf_fin_kernel(float* out) {
    const int lane = threadIdx.x;
    double a = 0.0;
    long long c = 0;
    for (int i = lane; i < NWARPS; i += 32) {
        a += g_pacc[i];
        c += (long long)g_pchars[i];
    }
#pragma unroll
    for (int off = 16; off > 0; off >>= 1) {
        a += __shfl_down_sync(0xffffffffu, a, off);
        c += __shfl_down_sync(0xffffffffu, c, off);
    }
    if (lane == 0) out[0] = (float)(a / (double)c);
}

extern "C" void kernel_launch(void* const* d_in, const int* in_sizes, int n_in,
                              void* d_out, int out_size)
{
    const float* bert  = (const float*)d_in[0];
    const int*   mask  = (const int*)d_in[1];
    const int*   tags  = (const int*)d_in[2];
    const float* trans = (const float*)d_in[3];
    float* out = (float*)d_out;

    crf_main_kernel<<<NWARPS, 32>>>(bert, mask, tags, trans);
    crf_fin_kernel<<<1, 32>>>(out);
}

// round 4
// speedup vs baseline: 1.7307x; 1.2127x over previous
#include <cuda_runtime.h>

#define NTAG 9
#define SEQ  512
#define BATCH 4096
#define SPW 3                                   // sequences per warp (9 lanes each)
#define WARPS_PER_CTA 4
#define SEQ_PER_CTA (SPW * WARPS_PER_CTA)       // 12
#define NCTA ((BATCH + SEQ_PER_CTA - 1) / SEQ_PER_CTA)  // 342

// Per-CTA partials, written unconditionally every launch (no init kernel).
__device__ double g_pacc[NCTA];
__device__ int    g_pchars[NCTA];

__global__ void __launch_bounds__(128) crf_scan_kernel(
    const float* __restrict__ bert,  // [B, S, 9] f32
    const int* __restrict__ mask,    // [B, S] i32
    const int* __restrict__ tags,    // [B, S] i32 (JAX x64 off: int32)
    const float* __restrict__ trans) // [11, 11] f32
{
    __shared__ float  sT[121];
    __shared__ double sAcc;
    __shared__ int    sChars;

    const int tid = threadIdx.x;
    if (tid < 121) sT[tid] = trans[tid];
    if (tid == 0) { sAcc = 0.0; sChars = 0; }
    __syncthreads();

    const int lane  = tid & 31;
    const int wid   = tid >> 5;
    const int g     = lane / 9;          // group 0..2 (3 = idle lanes 27-31)
    const int j     = lane - g * 9;      // tag owned by this lane, 0..8
    const int gbase = g * 9;

    const int  seq   = blockIdx.x * SEQ_PER_CTA + wid * SPW + g;
    const bool valid = (g < 3) && (seq < BATCH);
    const int  bc    = valid ? seq : 0;  // clamped for safe loads

    const float* em = bert + (size_t)bc * (SEQ * NTAG);
    const int*   mk = mask + (size_t)bc * SEQ;
    const int*   tg = tags + (size_t)bc * SEQ;

    // E column for this lane: E[i] = exp(T[i][j]); plus end-transition factor.
    float E[NTAG];
#pragma unroll
    for (int i = 0; i < NTAG; i++) E[i] = __expf(sT[i * 11 + j]);
    const float Eend = __expf(sT[j * 11 + 10]);

    // ---- length: 9 lanes of the group cooperatively sum the mask ----
    int Lp = 0;
    {
        const int4* mk4 = reinterpret_cast<const int4*>(mk);
#pragma unroll
        for (int q = 0; q < 15; q++) {
            int idx = j + 9 * q;
            if (idx < SEQ / 4) { int4 v = mk4[idx]; Lp += v.x + v.y + v.z + v.w; }
        }
    }
    int L = 0;
#pragma unroll
    for (int i = 0; i < NTAG; i++) L += __shfl_sync(0xffffffffu, Lp, gbase + i);
    if (!valid) L = 0;

    int maxL = L;
#pragma unroll
    for (int o = 16; o; o >>= 1) maxL = max(maxL, __shfl_xor_sync(0xffffffffu, maxL, o));

    // ---- t = 0 init (prob domain: alpha_j = eAcc*ln2 + log W_j) ----
    float W    = __expf(sT[99 + j] + __ldg(em + j));
    int   eAcc = 0;
    float real = 0.0f;
    int   prev = 0;
    {
        int tag0 = __ldg(tg);
        if (j == 0) {                    // group leader tracks the gold path
            prev = tag0;
            real = sT[99 + tag0] + __ldg(em + tag0);
        }
    }

    // Prefetch for t = 1.
    float emv  = __ldg(em + NTAG + j);
    int   tagc = __ldg(tg + 1);

    // ---- forward scan ----
#pragma unroll 4
    for (int t = 1; t < maxL; ++t) {
        // prefetch t+1 (clamped; independent of the alpha chain)
        const int   tn       = min(t + 1, SEQ - 1);
        const float em_next  = __ldg(em + tn * NTAG + j);
        const int   tag_next = __ldg(tg + tn);

        // broadcast the group's W vector (one shfl serves all 3 groups)
        float w[NTAG];
#pragma unroll
        for (int i = 0; i < NTAG; i++) w[i] = __shfl_sync(0xffffffffu, W, gbase + i);

        // matvec: acc = sum_i w_i * E[i][j]
        float acc = w[0] * E[0];
#pragma unroll
        for (int i = 1; i < NTAG; i++) acc = fmaf(w[i], E[i], acc);

        const float X   = __expf(emv);   // independent of W chain
        const bool  act = (t < L);       // group-uniform

        // exact power-of-2 rescale every 4 steps, from already-gathered w[]
        if ((t & 3) == 0) {
            float mx = w[0];
#pragma unroll
            for (int i = 1; i < NTAG; i++) mx = fmaxf(mx, w[i]);
            const int e = ((__float_as_int(mx) >> 23) & 255) - 127;
            acc *= __int_as_float((127 - e) << 23);
            if (act) eAcc += e;
        }

        const float Wn = acc * X;
        if (act) W = Wn;

        // gold path (leader lane only, off the alpha chain)
        if (j == 0 && act) {
            real += sT[prev * 11 + tagc] + __ldg(em + t * NTAG + tagc);
            prev = tagc;
        }

        emv  = em_next;
        tagc = tag_next;
    }

    // ---- termination: logsumexp over the group ----
    const float v = W * Eend;
    float s = 0.0f;
#pragma unroll
    for (int i = 0; i < NTAG; i++) s += __shfl_sync(0xffffffffu, v, gbase + i);

    if (j == 0 && valid) {
        real += sT[prev * 11 + 10];
        double total   = (double)eAcc * 0.6931471805599453 + (double)__logf(s);
        double contrib = total - (double)real;
        atomicAdd(&sAcc, contrib);
        atomicAdd(&sChars, L);
    }
    __syncthreads();
    if (tid == 0) {
        g_pacc[blockIdx.x]   = sAcc;
        g_pchars[blockIdx.x] = sChars;
    }
}

__global__ void crf_fin_kernel(float* out) {
    __shared__ double    sa[128];
    __shared__ long long sc[128];
    const int tid = threadIdx.x;
    double a = 0.0;
    long long c = 0;
    for (int i = tid; i < NCTA; i += 128) {
        a += g_pacc[i];
        c += (long long)g_pchars[i];
    }
    sa[tid] = a; sc[tid] = c;
    __syncthreads();
    for (int o = 64; o; o >>= 1) {
        if (tid < o) { sa[tid] += sa[tid + o]; sc[tid] += sc[tid + o]; }
        __syncthreads();
    }
    if (tid == 0) out[0] = (float)(sa[0] / (double)sc[0]);
}

extern "C" void kernel_launch(void* const* d_in, const int* in_sizes, int n_in,
                              void* d_out, int out_size)
{
    const float* bert  = (const float*)d_in[0];
    const int*   mask  = (const int*)d_in[1];
    const int*   tags  = (const int*)d_in[2];
    const float* trans = (const float*)d_in[3];
    float* out = (float*)d_out;

    crf_scan_kernel<<<NCTA, 128>>>(bert, mask, tags, trans);
    crf_fin_kernel<<<1, 128>>>(out);
}